// round 8
// baseline (speedup 1.0000x reference)
#include <cuda_runtime.h>
#include <math.h>

#define B_ 8
#define T_ 512
#define C_ 512
#define H_ 8
#define F_ 2048
#define WIN_ 10
#define TP_ 516

#define ELT_X (B_*C_*T_)
#define ELT_P (B_*H_*T_*T_)
#define ELT_XP (B_*C_*TP_)
#define ELT_HP (B_*F_*TP_)
#define WQKV ((size_t)6*C_*C_)
#define WFF  ((size_t)6*F_*C_*3)

__device__ float g_pool[(size_t)7*ELT_X + ELT_P + ELT_XP + ELT_HP + 4*WQKV + 2*WFF];

__device__ __forceinline__ unsigned f2tf(float x){
    unsigned y; asm("cvt.rna.tf32.f32 %0, %1;" : "=r"(y) : "f"(x)); return y;
}
__device__ __forceinline__ float f2tfr(float x){ return __uint_as_float(f2tf(x)); }
__device__ __forceinline__ void mma_tf32(float c[4], const unsigned a[4], const unsigned b[2]){
    asm("mma.sync.aligned.m16n8k8.row.col.f32.tf32.tf32.f32 "
        "{%0,%1,%2,%3}, {%4,%5,%6,%7}, {%8,%9}, {%0,%1,%2,%3};"
        : "+f"(c[0]), "+f"(c[1]), "+f"(c[2]), "+f"(c[3])
        : "r"(a[0]), "r"(a[1]), "r"(a[2]), "r"(a[3]), "r"(b[0]), "r"(b[1]));
}
__device__ __forceinline__ void cp16(void* smem, const void* g){
    unsigned s = (unsigned)__cvta_generic_to_shared(smem);
    asm volatile("cp.async.ca.shared.global [%0], [%1], 16;" :: "r"(s), "l"(g));
}
#define CP_COMMIT asm volatile("cp.async.commit_group;" ::: "memory")
#define CP_WAIT0  asm volatile("cp.async.wait_group 0;" ::: "memory")

/* weight swizzle: [M][Ktot] -> [M/128][Ktot/16][2048] fragment-ready order */
__global__ void k_swizA(const float* __restrict__ S, float* __restrict__ D,
                        int Ktot, size_t msz, size_t total)
{
    size_t idx = (size_t)blockIdx.x*256 + threadIdx.x;
    if (idx >= total) return;
    size_t l = idx / msz;
    int od = (int)(idx - l*msz);
    int mtile = od / (Ktot*128);
    int rem = od - mtile*(Ktot*128);
    int ktile = rem >> 11;
    int rem2 = rem & 2047;
    int mgrp = rem2 >> 8;
    int rem3 = rem2 & 255;
    int ks = rem3 >> 7;
    int rem4 = rem3 & 127;
    int lane4 = rem4 >> 2;
    int u = rem4 & 3;
    int gid = lane4 >> 2, tig = lane4 & 3;
    int m = mtile*128 + mgrp*16 + gid + (u&1)*8;
    int k = ktile*16 + ks*8 + tig + (u>>1)*4;
    D[idx] = f2tfr(S[l*msz + (size_t)m*Ktot + k]);
}

__global__ void k_maskmul2(const float* __restrict__ X, const float* __restrict__ mask,
                           float* __restrict__ Y, float* __restrict__ Yr)
{
    int i = blockIdx.x*256 + threadIdx.x;
    int t = i & (T_-1);
    int b = i / (C_*T_);
    float v = X[i] * mask[b*T_ + t];
    Y[i] = v; Yr[i] = f2tfr(v);
}
__global__ void k_maskmul(const float* __restrict__ X, const float* __restrict__ mask,
                          float* __restrict__ Y)
{
    int i = blockIdx.x*256 + threadIdx.x;
    int t = i & (T_-1);
    int b = i / (C_*T_);
    Y[i] = X[i] * mask[b*T_ + t];
}

__global__ void k_zb(float* __restrict__ Xp, float* __restrict__ Hp)
{
    int r = blockIdx.x*256 + threadIdx.x;
    float* base = (r < B_*C_) ? (Xp + (size_t)r*TP_) : (Hp + (size_t)(r - B_*C_)*TP_);
    base[0]=0.f; base[513]=0.f; base[514]=0.f; base[515]=0.f;
}

/* fragment-swizzled A load: 1 x LDS.128 per i */
#define LOAD_AF(af, sAblk, wm, ks1, lane) \
    _Pragma("unroll") \
    for (int i=0;i<4;i++){ \
        const float4 av = *(const float4*)((sAblk) + ((((wm)*4+i)*2+(ks1))<<7) + ((lane)<<2)); \
        af[i][0]=__float_as_uint(av.x); af[i][1]=__float_as_uint(av.y); \
        af[i][2]=__float_as_uint(av.z); af[i][3]=__float_as_uint(av.w); \
    }

/* =========== 1x1 GEMM (Wo), swizzled W, KSTEP=32, 2-stage ============ */
__launch_bounds__(256,2)
__global__ void g1x1(const float* __restrict__ Wm, const float* __restrict__ X,
                     const float* __restrict__ bias, float* __restrict__ Y)
{
    extern __shared__ float sm[];
    float* sA = sm;                 /* [2][4096] */
    float* sB = sm + 8192;          /* [2][32][136] */
    const int n0 = blockIdx.x*128;
    const int m0 = blockIdx.y*128;
    const int b  = blockIdx.z;
    const int tid = threadIdx.x;
    const int lane = tid & 31, wid = tid >> 5;
    const int gid = lane >> 2, tig = lane & 3;
    const int wm = wid & 1, wn = wid >> 1;

    const float* xb = X + (size_t)b*C_*T_;
    const int rowB = tid >> 4, colB = (tid & 15)*8;

    float acc[4][4][4];
#pragma unroll
    for (int i=0;i<4;i++)
#pragma unroll
        for (int j=0;j<4;j++)
#pragma unroll
            for (int u=0;u<4;u++) acc[i][j][u]=0.f;

    const int KT = C_/32;
#define ST_A(st,K0) { const float* ap = Wm + (size_t)(m0>>7)*((size_t)C_<<7) + ((size_t)((K0)>>4)<<11) + (tid<<4); \
                      float* d = sA + (st)*4096 + tid*16; \
                      cp16(d,ap); cp16(d+4,ap+4); cp16(d+8,ap+8); cp16(d+12,ap+12); }
#define ST_B(st,K0) { const float* bp = xb + (size_t)((K0)+rowB)*T_ + n0 + colB; \
                      float* d = sB + (st)*4352 + rowB*136 + colB; \
                      cp16(d,bp); cp16(d+4,bp+4); \
                      const float* bp2 = bp + 16*T_; float* d2 = d + 16*136; \
                      cp16(d2,bp2); cp16(d2+4,bp2+4); }
    ST_A(0,0) ST_B(0,0) CP_COMMIT;

    for (int kt=0; kt<KT; kt++){
        CP_WAIT0;
        __syncthreads();
        if (kt+1 < KT){ int st=(kt+1)&1; int K0=(kt+1)*32; ST_A(st,K0) ST_B(st,K0) CP_COMMIT; }
        const int buf = kt&1;
        float* sAb = sA + buf*4096;
        float* sBb = sB + buf*4352;
#pragma unroll
        for (int ks=0;ks<4;ks++){
            unsigned af[4][4], bf[4][2];
            LOAD_AF(af, sAb + (ks>>1)*2048, wm, ks&1, lane)
#pragma unroll
            for (int j=0;j<4;j++){
                int c = wn*32 + j*8 + gid;
                bf[j][0]=__float_as_uint(sBb[(ks*8+tig  )*136 + c]);
                bf[j][1]=__float_as_uint(sBb[(ks*8+tig+4)*136 + c]);
            }
#pragma unroll
            for (int i=0;i<4;i++)
#pragma unroll
                for (int j=0;j<4;j++) mma_tf32(acc[i][j], af[i], bf[j]);
        }
        if (kt+1 < KT) __syncthreads();
    }
#undef ST_A
#undef ST_B

#pragma unroll
    for (int i=0;i<4;i++){
        int row = m0 + wm*64 + i*16 + gid;
        float bv0 = bias[row], bv8 = bias[row+8];
        float* y0 = Y + (size_t)(b*C_ + row)*T_;
        float* y8 = Y + (size_t)(b*C_ + row+8)*T_;
#pragma unroll
        for (int j=0;j<4;j++){
            int col = n0 + wn*32 + j*8 + tig*2;
            *(float2*)(y0+col)=make_float2(acc[i][j][0]+bv0, acc[i][j][1]+bv0);
            *(float2*)(y8+col)=make_float2(acc[i][j][2]+bv8, acc[i][j][3]+bv8);
        }
    }
}

/* =========== fused Q/K/V, swizzled W, KSTEP=32, 2-stage ============ */
__launch_bounds__(256,2)
__global__ void g_qkv(const float* __restrict__ X,
                      const float* __restrict__ Wq, const float* __restrict__ Wk, const float* __restrict__ Wv,
                      const float* __restrict__ bq, const float* __restrict__ bk, const float* __restrict__ bv,
                      float* __restrict__ Yq, float* __restrict__ Yk, float* __restrict__ Yv)
{
    extern __shared__ float sm[];
    float* sA = sm;
    float* sB = sm + 8192;
    const int n0 = blockIdx.x*128;
    const int mi = blockIdx.y;
    const int sel = mi >> 2;
    const int m0 = (mi & 3)*128;
    const int b  = blockIdx.z;
    const float* Wm  = (sel==0)?Wq:(sel==1)?Wk:Wv;
    const float* bias= (sel==0)?bq:(sel==1)?bk:bv;
    const float alpha= (sel==0)?0.125f:1.f;

    const int tid = threadIdx.x;
    const int lane = tid & 31, wid = tid >> 5;
    const int gid = lane >> 2, tig = lane & 3;
    const int wm = wid & 1, wn = wid >> 1;

    const float* xb = X + (size_t)b*C_*T_;
    const int rowB = tid >> 4, colB = (tid & 15)*8;

    float acc[4][4][4];
#pragma unroll
    for (int i=0;i<4;i++)
#pragma unroll
        for (int j=0;j<4;j++)
#pragma unroll
            for (int u=0;u<4;u++) acc[i][j][u]=0.f;

    const int KT = C_/32;
#define ST_A(st,K0) { const float* ap = Wm + (size_t)(m0>>7)*((size_t)C_<<7) + ((size_t)((K0)>>4)<<11) + (tid<<4); \
                      float* d = sA + (st)*4096 + tid*16; \
                      cp16(d,ap); cp16(d+4,ap+4); cp16(d+8,ap+8); cp16(d+12,ap+12); }
#define ST_B(st,K0) { const float* bp = xb + (size_t)((K0)+rowB)*T_ + n0 + colB; \
                      float* d = sB + (st)*4352 + rowB*136 + colB; \
                      cp16(d,bp); cp16(d+4,bp+4); \
                      const float* bp2 = bp + 16*T_; float* d2 = d + 16*136; \
                      cp16(d2,bp2); cp16(d2+4,bp2+4); }
    ST_A(0,0) ST_B(0,0) CP_COMMIT;

    for (int kt=0; kt<KT; kt++){
        CP_WAIT0;
        __syncthreads();
        if (kt+1 < KT){ int st=(kt+1)&1; int K0=(kt+1)*32; ST_A(st,K0) ST_B(st,K0) CP_COMMIT; }
        const int buf = kt&1;
        float* sAb = sA + buf*4096;
        float* sBb = sB + buf*4352;
#pragma unroll
        for (int ks=0;ks<4;ks++){
            unsigned af[4][4], bf[4][2];
            LOAD_AF(af, sAb + (ks>>1)*2048, wm, ks&1, lane)
#pragma unroll
            for (int j=0;j<4;j++){
                int c = wn*32 + j*8 + gid;
                bf[j][0]=__float_as_uint(sBb[(ks*8+tig  )*136 + c]);
                bf[j][1]=__float_as_uint(sBb[(ks*8+tig+4)*136 + c]);
            }
#pragma unroll
            for (int i=0;i<4;i++)
#pragma unroll
                for (int j=0;j<4;j++) mma_tf32(acc[i][j], af[i], bf[j]);
        }
        if (kt+1 < KT) __syncthreads();
    }
#undef ST_A
#undef ST_B

    if (sel==1){
#pragma unroll
        for (int i=0;i<4;i++){
            int row = m0 + wm*64 + i*16 + gid;
            float bv0 = bias[row], bv8 = bias[row+8];
            float* y0 = Yk + (size_t)(b*C_ + row)*T_;
            float* y8 = Yk + (size_t)(b*C_ + row+8)*T_;
#pragma unroll
            for (int j=0;j<4;j++){
                int col = n0 + wn*32 + j*8 + tig*2;
                *(float2*)(y0+col)=make_float2(f2tfr(acc[i][j][0]+bv0), f2tfr(acc[i][j][1]+bv0));
                *(float2*)(y8+col)=make_float2(f2tfr(acc[i][j][2]+bv8), f2tfr(acc[i][j][3]+bv8));
            }
        }
    } else {
        float* Yt = (sel==0)?Yq:Yv;
#pragma unroll
        for (int i=0;i<4;i++){
            int row = m0 + wm*64 + i*16 + gid;
            float bv0 = bias[row], bv8 = bias[row+8];
            int h0 = row>>6, d0v = row&63;
            int h8 = (row+8)>>6, d8v = (row+8)&63;
            float* base0 = Yt + ((size_t)(b*H_+h0)*T_)*64 + d0v;
            float* base8 = Yt + ((size_t)(b*H_+h8)*T_)*64 + d8v;
#pragma unroll
            for (int j=0;j<4;j++){
                int col = n0 + wn*32 + j*8 + tig*2;
                base0[(size_t)col*64]     = f2tfr(alpha*(acc[i][j][0]+bv0));
                base0[(size_t)(col+1)*64] = f2tfr(alpha*(acc[i][j][1]+bv0));
                base8[(size_t)col*64]     = f2tfr(alpha*(acc[i][j][2]+bv8));
                base8[(size_t)(col+1)*64] = f2tfr(alpha*(acc[i][j][3]+bv8));
            }
        }
    }
}

/* =========== scores, KSTEP=32, 2-stage; A unswizzled (pad 36) ============ */
__launch_bounds__(256,2)
__global__ void g_sc(const float* __restrict__ Qt, const float* __restrict__ Kc,
                     float* __restrict__ P)
{
    extern __shared__ float sm[];
    float* sA = sm;                  /* [2][128][36] */
    float* sB = sm + 2*128*36;       /* [2][32][136] */
    const int s0 = blockIdx.x*128;
    const int t0 = blockIdx.y*128;
    const int bh = blockIdx.z;
    const int tid = threadIdx.x;
    const int lane = tid & 31, wid = tid >> 5;
    const int gid = lane >> 2, tig = lane & 3;
    const int wm = wid & 1, wn = wid >> 1;

    const float* qb = Qt + (size_t)bh*T_*64;
    const float* kb = Kc + (size_t)bh*64*T_;
    const int rowA = tid >> 1, colA = (tid & 1)*16;
    const int rowB = tid >> 4, colB = (tid & 15)*8;

    float acc[4][4][4];
#pragma unroll
    for (int i=0;i<4;i++)
#pragma unroll
        for (int j=0;j<4;j++)
#pragma unroll
            for (int u=0;u<4;u++) acc[i][j][u]=0.f;

#define ST_A(st,K0) { const float* ap = qb + (size_t)(t0+rowA)*64 + (K0) + colA; \
                      float* d = sA + (st)*4608 + rowA*36 + colA; \
                      cp16(d,ap); cp16(d+4,ap+4); cp16(d+8,ap+8); cp16(d+12,ap+12); }
#define ST_B(st,K0) { const float* bp = kb + (size_t)((K0)+rowB)*T_ + s0 + colB; \
                      float* d = sB + (st)*4352 + rowB*136 + colB; \
                      cp16(d,bp); cp16(d+4,bp+4); \
                      const float* bp2 = bp + 16*T_; float* d2 = d + 16*136; \
                      cp16(d2,bp2); cp16(d2+4,bp2+4); }
    ST_A(0,0) ST_B(0,0) CP_COMMIT;

    for (int kt=0; kt<2; kt++){
        CP_WAIT0;
        __syncthreads();
        if (kt==0){ ST_A(1,32) ST_B(1,32) CP_COMMIT; }
        const int buf = kt&1;
        float* sAb = sA + buf*4608;
        float* sBb = sB + buf*4352;
#pragma unroll
        for (int ks=0;ks<4;ks++){
            unsigned af[4][4], bf[4][2];
#pragma unroll
            for (int i=0;i<4;i++){
                int r = wm*64 + i*16 + gid;
                af[i][0]=__float_as_uint(sAb[(r  )*36 + ks*8+tig  ]);
                af[i][1]=__float_as_uint(sAb[(r+8)*36 + ks*8+tig  ]);
                af[i][2]=__float_as_uint(sAb[(r  )*36 + ks*8+tig+4]);
                af[i][3]=__float_as_uint(sAb[(r+8)*36 + ks*8+tig+4]);
            }
#pragma unroll
            for (int j=0;j<4;j++){
                int c = wn*32 + j*8 + gid;
                bf[j][0]=__float_as_uint(sBb[(ks*8+tig  )*136 + c]);
                bf[j][1]=__float_as_uint(sBb[(ks*8+tig+4)*136 + c]);
            }
#pragma unroll
            for (int i=0;i<4;i++)
#pragma unroll
                for (int j=0;j<4;j++) mma_tf32(acc[i][j], af[i], bf[j]);
        }
        if (kt==0) __syncthreads();
    }
#undef ST_A
#undef ST_B

#pragma unroll
    for (int i=0;i<4;i++){
        int row = t0 + wm*64 + i*16 + gid;
        float* y0 = P + ((size_t)bh*T_ + row)*T_;
        float* y8 = P + ((size_t)bh*T_ + row+8)*T_;
#pragma unroll
        for (int j=0;j<4;j++){
            int col = s0 + wn*32 + j*8 + tig*2;
            *(float2*)(y0+col)=make_float2(acc[i][j][0], acc[i][j][1]);
            *(float2*)(y8+col)=make_float2(acc[i][j][2], acc[i][j][3]);
        }
    }
}

/* =========== ctx + rel-V band, KSTEP=32, 2-stage ============ */
__launch_bounds__(256,2)
__global__ void g_ctx(const float* __restrict__ P, const float* __restrict__ Vt,
                      const float* __restrict__ erv, float* __restrict__ CTX)
{
    extern __shared__ float sm[];
    float* sA = sm;                  /* [2][128][36] */
    float* sB = sm + 2*128*36;       /* [2][32][72]  */
    float* sErv = sB + 2*32*72;      /* [21*64]      */
    const int t0 = blockIdx.x*128;
    const int bh = blockIdx.y;
    const int b  = bh >> 3, h = bh & 7;
    const int tid = threadIdx.x;
    const int lane = tid & 31, wid = tid >> 5;
    const int gid = lane >> 2, tig = lane & 3;
    const int wm = wid & 1, wn = wid >> 1;

    const float* pb = P + (size_t)bh*T_*T_;
    const float* vb = Vt + (size_t)bh*T_*64;
    const int rowA = tid >> 1, colA = (tid & 1)*16;
    const int rowB = tid >> 4, colB = (tid & 15)*4;

    for (int l=tid; l<21*64; l+=256) sErv[l]=erv[l];

    float acc[4][2][4];
#pragma unroll
    for (int i=0;i<4;i++)
#pragma unroll
        for (int j=0;j<2;j++)
#pragma unroll
            for (int u=0;u<4;u++) acc[i][j][u]=0.f;

#define ST_A(st,K0) { const float* ap = pb + (size_t)(t0+rowA)*T_ + (K0) + colA; \
                      float* d = sA + (st)*4608 + rowA*36 + colA; \
                      cp16(d,ap); cp16(d+4,ap+4); cp16(d+8,ap+8); cp16(d+12,ap+12); }
#define ST_B(st,K0) { const float* bp = vb + (size_t)((K0)+rowB)*64 + colB; \
                      float* d = sB + (st)*2304 + rowB*72 + colB; \
                      cp16(d,bp); \
                      const float* bp2 = bp + 16*64; float* d2 = d + 16*72; \
                      cp16(d2,bp2); }
    ST_A(0,0) ST_B(0,0) CP_COMMIT;

    const int KT = T_/32;
    for (int kt=0; kt<KT; kt++){
        CP_WAIT0;
        __syncthreads();
        if (kt+1 < KT){ int st=(kt+1)&1; int K0=(kt+1)*32; ST_A(st,K0) ST_B(st,K0) CP_COMMIT; }
        const int buf = kt&1;
        float* sAb = sA + buf*4608;
        float* sBb = sB + buf*2304;
#pragma unroll
        for (int ks=0;ks<4;ks++){
            unsigned af[4][4], bf[2][2];
#pragma unroll
            for (int i=0;i<4;i++){
                int r = wm*64 + i*16 + gid;
                af[i][0]=__float_as_uint(sAb[(r  )*36 + ks*8+tig  ]);
                af[i][1]=__float_as_uint(sAb[(r+8)*36 + ks*8+tig  ]);
                af[i][2]=__float_as_uint(sAb[(r  )*36 + ks*8+tig+4]);
                af[i][3]=__float_as_uint(sAb[(r+8)*36 + ks*8+tig+4]);
            }
#pragma unroll
            for (int j=0;j<2;j++){
                int c = wn*16 + j*8 + gid;
                bf[j][0]=__float_as_uint(sBb[(ks*8+tig  )*72 + c]);
                bf[j][1]=__float_as_uint(sBb[(ks*8+tig+4)*72 + c]);
            }
#pragma unroll
            for (int i=0;i<4;i++)
#pragma unroll
                for (int j=0;j<2;j++) mma_tf32(acc[i][j], af[i], bf[j]);
        }
        if (kt+1 < KT) __syncthreads();
    }
#undef ST_A
#undef ST_B

#pragma unroll
    for (int i=0;i<4;i++){
#pragma unroll
        for (int rr=0; rr<2; rr++){
            int t = t0 + wm*64 + i*16 + gid + rr*8;
            const float* prow = pb + (size_t)t*T_;
            for (int r=0;r<21;r++){
                int s = t + r - WIN_;
                if ((unsigned)s < (unsigned)T_){
                    float pv = prow[s];
#pragma unroll
                    for (int j=0;j<2;j++){
                        int d = wn*16 + j*8 + tig*2;
                        acc[i][j][rr*2+0] += pv*sErv[r*64 + d];
                        acc[i][j][rr*2+1] += pv*sErv[r*64 + d+1];
                    }
                }
            }
        }
    }

#pragma unroll
    for (int i=0;i<4;i++){
        int row = t0 + wm*64 + i*16 + gid;
#pragma unroll
        for (int j=0;j<2;j++){
            int d = wn*16 + j*8 + tig*2;
            float* c0 = CTX + (size_t)(b*C_ + h*64 + d)*T_;
            float* c1 = CTX + (size_t)(b*C_ + h*64 + d+1)*T_;
            c0[row]   = f2tfr(acc[i][j][0]);
            c1[row]   = f2tfr(acc[i][j][1]);
            c0[row+8] = f2tfr(acc[i][j][2]);
            c1[row+8] = f2tfr(acc[i][j][3]);
        }
    }
}

/* =========== K=3 conv GEMM: swizzled A + raw-row B, KSTEP=32, 2-stage =========== */
__launch_bounds__(256,2)
__global__ void gconv3p(const float* __restrict__ Xp, const float* __restrict__ Wm,
                        const float* __restrict__ bias, const float* __restrict__ mask,
                        float* __restrict__ Y, int Cin, int Cout,
                        int mode, int ktiles)
{
    __shared__ float sA[2][4096];
    __shared__ float sX[2][12][136];
    const int n0 = blockIdx.x*128;
    const int m0 = blockIdx.y*128;
    const int bz = blockIdx.z;
    const int b    = (mode==1) ? (bz & 7) : bz;
    const int part = (mode==1) ? (bz >> 3) : 0;
    const int kOff = part*(ktiles*32);

    const int tid = threadIdx.x;
    const int lane = tid & 31, wid = tid >> 5;
    const int gid = lane >> 2, tig = lane & 3;
    const int wm = wid & 1, wn = wid >> 1;

    const float* xpb = Xp + (size_t)b*Cin*TP_;
    const int Ktot = Cin*3;

    float acc[4][4][4];
#pragma unroll
    for (int i=0;i<4;i++)
#pragma unroll
        for (int j=0;j<4;j++)
#pragma unroll
            for (int u=0;u<4;u++) acc[i][j][u]=0.f;

#define ST_A(st,K0) { const float* ap = Wm + (size_t)(m0>>7)*((size_t)Ktot<<7) + ((size_t)((K0)>>4)<<11) + (tid<<4); \
                      float* d = &sA[st][tid*16]; \
                      cp16(d,ap); cp16(d+4,ap+4); cp16(d+8,ap+8); cp16(d+12,ap+12); }
#define ST_B(st,K0) { int cc0 = (K0)/3; \
                      { int rB=tid/33, cB=tid-rB*33; if (tid<396-256 || 1){} \
                        if (tid < 396){ \
                          const float* bp = xpb + (size_t)(cc0+rB)*TP_ + n0 + cB*4; \
                          cp16(&sX[st][rB][cB*4], bp); } } \
                      { int slot = tid+256; if (slot < 396){ int rB=slot/33, cB=slot-rB*33; \
                          const float* bp = xpb + (size_t)(cc0+rB)*TP_ + n0 + cB*4; \
                          cp16(&sX[st][rB][cB*4], bp); } } }
    ST_A(0,kOff) ST_B(0,kOff) CP_COMMIT;

    for (int kt=0; kt<ktiles; kt++){
        CP_WAIT0;
        __syncthreads();
        if (kt+1 < ktiles){ int st=(kt+1)&1; int K0=kOff+(kt+1)*32; ST_A(st,K0) ST_B(st,K0) CP_COMMIT; }
        const int buf = kt&1;
        const int Kbase = kOff + kt*32;
        const int cc0t = Kbase/3;
        const float* sAb = &sA[buf][0];
#pragma unroll
        for (int ks=0;ks<4;ks++){
            int kg0 = Kbase + ks*8 + tig;
            int kg1 = kg0 + 4;
            int q0 = kg0/3, q1 = kg1/3;
            int r0 = q0 - cc0t, k0 = kg0 - q0*3;
            int r1 = q1 - cc0t, k1 = kg1 - q1*3;
            unsigned af[4][4], bf[4][2];
            LOAD_AF(af, sAb + (ks>>1)*2048, wm, ks&1, lane)
#pragma unroll
            for (int j=0;j<4;j++){
                int c = wn*32 + j*8 + gid;
                bf[j][0]=__float_as_uint(sX[buf][r0][c + k0]);
                bf[j][1]=__float_as_uint(sX[buf][r1][c + k1]);
            }
#pragma unroll
            for (int i=0;i<4;i++)
#pragma unroll
                for (int j=0;j<4;j++) mma_tf32(acc[i][j], af[i], bf[j]);
        }
        if (kt+1 < ktiles) __syncthreads();
    }
#undef ST_A
#undef ST_B

    if (mode==0){
        const float* mb = mask + b*T_;
#pragma unroll
        for (int i=0;i<4;i++){
            int row = m0 + wm*64 + i*16 + gid;
            float bv0 = bias[row], bv8 = bias[row+8];
            float* y0 = Y + (size_t)(b*Cout + row)*TP_ + 1;
            float* y8 = Y + (size_t)(b*Cout + row+8)*TP_ + 1;
#pragma unroll
            for (int j=0;j<4;j++){
                int col = n0 + wn*32 + j*8 + tig*2;
                float m0v = mb[col], m1v = mb[col+1];
                y0[col]   = f2tfr(fmaxf(acc[i][j][0]+bv0, 0.f)*m0v);
                y0[col+1] = f2tfr(fmaxf(acc[i][j][1]+bv0, 0.f)*m1v);
                y8[col]   = f2tfr(fmaxf(acc[i][j][2]+bv8, 0.f)*m0v);
                y8[col+1] = f2tfr(fmaxf(acc[i][j][3]+bv8, 0.f)*m1v);
            }
        }
    } else {
#pragma unroll
        for (int i=0;i<4;i++){
            int row = m0 + wm*64 + i*16 + gid;
            float* y0 = Y + (size_t)part*ELT_X + (size_t)(b*Cout + row)*T_;
            float* y8 = Y + (size_t)part*ELT_X + (size_t)(b*Cout + row+8)*T_;
#pragma unroll
            for (int j=0;j<4;j++){
                int col = n0 + wn*32 + j*8 + tig*2;
                *(float2*)(y0+col)=make_float2(acc[i][j][0], acc[i][j][1]);
                *(float2*)(y8+col)=make_float2(acc[i][j][2], acc[i][j][3]);
            }
        }
    }
}

/* ---------------- split-K reduce + bias + mask ---------------- */
__global__ void k_red(const float* __restrict__ P0, const float* __restrict__ bias,
                      const float* __restrict__ mask, float* __restrict__ Y)
{
    int i = blockIdx.x*256 + threadIdx.x;
    int t = i & (T_-1);
    int o = (i >> 9) & (C_-1);
    int b = i >> 18;
    Y[i] = (P0[i] + P0[(size_t)ELT_X + i] + bias[o]) * mask[b*T_ + t];
}

/* ---------------- banded relative-K logits ---------------- */
__global__ void k_relband(const float* __restrict__ Qt, const float* __restrict__ erk,
                          float* __restrict__ P)
{
    const int bh = blockIdx.y;
    const int t = blockIdx.x*8 + (threadIdx.x>>5);
    const int lane = threadIdx.x & 31;
    const float* qr = Qt + ((size_t)bh*T_ + t)*64;
    float q0 = qr[lane];
    float q1 = qr[32+lane];
    float* prow = P + ((size_t)bh*T_ + t)*T_;
    for (int r=0;r<21;r++){
        float pd = q0*erk[r*64+lane] + q1*erk[r*64+32+lane];
#pragma unroll
        for (int o=16;o;o>>=1) pd += __shfl_xor_sync(0xffffffffu, pd, o);
        int s = t + r - WIN_;
        if (lane==0 && (unsigned)s < (unsigned)T_) prow[s] += pd;
    }
}

/* ---------------- row softmax with mask (rounded output) ---------------- */
__launch_bounds__(256)
__global__ void k_softmax(float* __restrict__ P, const float* __restrict__ mask)
{
    const int row = blockIdx.x;
    const int t  = row & (T_-1);
    const int bh = row >> 9;
    const int b  = bh >> 3;
    float* p = P + (size_t)row*T_;
    const float* mb = mask + b*T_;
    const int tid = threadIdx.x;
    const int lane = tid & 31, w = tid >> 5;
    const float mt = mb[t];
    float v0 = (mt*mb[tid]     != 0.f) ? p[tid]     : -1e4f;
    float v1 = (mt*mb[tid+256] != 0.f) ? p[tid+256] : -1e4f;
    __shared__ float red[8];
    float m = fmaxf(v0,v1);
#pragma unroll
    for (int o=16;o;o>>=1) m = fmaxf(m, __shfl_xor_sync(0xffffffffu, m, o));
    if (lane==0) red[w]=m;
    __syncthreads();
    float mx = red[0];
#pragma unroll
    for (int k2=1;k2<8;k2++) mx = fmaxf(mx, red[k2]);
    float e0 = expf(v0-mx), e1 = expf(v1-mx);
    float s = e0+e1;
#pragma unroll
    for (int o=16;o;o>>=1) s += __shfl_xor_sync(0xffffffffu, s, o);
    __syncthreads();
    if (lane==0) red[w]=s;
    __syncthreads();
    float tot = 0.f;
#pragma unroll
    for (int k2=0;k2<8;k2++) tot += red[k2];
    float inv = 1.f/tot;
    p[tid]=f2tfr(e0*inv); p[tid+256]=f2tfr(e1*inv);
}

/* ------- residual add + channel LN; optional padded / rounded copies -- */
__launch_bounds__(512)
__global__ void k_addln(float* __restrict__ X, const float* __restrict__ Yv,
                        const float* __restrict__ gamma, const float* __restrict__ beta,
                        float* __restrict__ Xp, float* __restrict__ Xr,
                        const float* __restrict__ mask)
{
    const int b = blockIdx.y;
    const int tl = threadIdx.x & 31;
    const int slot = threadIdx.x >> 5;
    const int t = blockIdx.x*32 + tl;
    __shared__ float ssum[16][33];
    __shared__ float ssq[16][33];
    float vals[32];
    float s=0.f, q=0.f;
    size_t base = (size_t)b*C_*T_ + t;
#pragma unroll
    for (int u=0;u<32;u++){
        int c = slot*32+u;
        float v = X[base + (size_t)c*T_] + Yv[base + (size_t)c*T_];
        vals[u]=v; s+=v; q+=v*v;
    }
    ssum[slot][tl]=s; ssq[slot][tl]=q;
    __syncthreads();
    float m=0.f, vv=0.f;
#pragma unroll
    for (int k2=0;k2<16;k2++){ m+=ssum[k2][tl]; vv+=ssq[k2][tl]; }
    m *= (1.f/512.f);
    vv = vv*(1.f/512.f) - m*m;
    float r = rsqrtf(vv + 1e-5f);
    float mk = Xp ? mask[b*T_ + t] : 0.f;
#pragma unroll
    for (int u=0;u<32;u++){
        int c = slot*32+u;
        float o = (vals[u]-m)*r*gamma[c] + beta[c];
        X[base + (size_t)c*T_] = o;
        if (Xp) Xp[((size_t)(b*C_+c))*TP_ + t + 1] = f2tfr(o*mk);
        if (Xr) Xr[base + (size_t)c*T_] = f2tfr(o);
    }
}

/* ---------------- host orchestration ---------------- */
extern "C" void kernel_launch(void* const* d_in, const int* in_sizes, int n_in,
                              void* d_out, int out_size)
{
    (void)in_sizes; (void)n_in; (void)out_size;
    const float* x_in = (const float*)d_in[0];
    const float* mask = (const float*)d_in[1];
    const float* Wq  = (const float*)d_in[2];
    const float* bq  = (const float*)d_in[3];
    const float* Wk  = (const float*)d_in[4];
    const float* bk  = (const float*)d_in[5];
    const float* Wv  = (const float*)d_in[6];
    const float* bv  = (const float*)d_in[7];
    const float* Wo  = (const float*)d_in[8];
    const float* bo  = (const float*)d_in[9];
    const float* erk = (const float*)d_in[10];
    const float* erv = (const float*)d_in[11];
    const float* g1  = (const float*)d_in[12];
    const float* b1  = (const float*)d_in[13];
    const float* g2  = (const float*)d_in[14];
    const float* b2  = (const float*)d_in[15];
    const float* W1  = (const float*)d_in[16];
    const float* bf1 = (const float*)d_in[17];
    const float* W2  = (const float*)d_in[18];
    const float* bf2 = (const float*)d_in[19];

    const int SM_GW  = (8192 + 2*32*136)*4;            /* g1x1 / g_qkv: 67584 B */
    const int SM_SC  = (2*128*36 + 2*32*136)*4;        /* g_sc: 71680 B */
    const int SM_CTX = (2*128*36 + 2*32*72 + 21*64)*4; /* g_ctx: 60672 B */
    cudaFuncSetAttribute(g1x1,  cudaFuncAttributeMaxDynamicSharedMemorySize, SM_GW);
    cudaFuncSetAttribute(g_qkv, cudaFuncAttributeMaxDynamicSharedMemorySize, SM_GW);
    cudaFuncSetAttribute(g_sc,  cudaFuncAttributeMaxDynamicSharedMemorySize, SM_SC);
    cudaFuncSetAttribute(g_ctx, cudaFuncAttributeMaxDynamicSharedMemorySize, SM_CTX);

    float* pool = 0;
    cudaGetSymbolAddress((void**)&pool, g_pool);
    float* px  = pool;
    float* pxr = pool + (size_t)1*ELT_X;
    float* pq  = pool + (size_t)2*ELT_X;
    float* pk  = pool + (size_t)3*ELT_X;
    float* pv  = pool + (size_t)4*ELT_X;
    float* pc  = pool + (size_t)5*ELT_X;
    float* py  = pool + (size_t)6*ELT_X;
    float* pp  = pool + (size_t)7*ELT_X;
    float* pxp = pool + (size_t)7*ELT_X + ELT_P;
    float* php = pool + (size_t)7*ELT_X + ELT_P + ELT_XP;
    float* wqr = php + ELT_HP;
    float* wkr = wqr + WQKV;
    float* wvr = wkr + WQKV;
    float* wor = wvr + WQKV;
    float* w1r = wor + WQKV;
    float* w2r = w1r + WFF;

    size_t mszQ = (size_t)C_*C_;
    k_swizA<<<(unsigned)((WQKV+255)/256),256>>>(Wq, wqr, C_, mszQ, WQKV);
    k_swizA<<<(unsigned)((WQKV+255)/256),256>>>(Wk, wkr, C_, mszQ, WQKV);
    k_swizA<<<(unsigned)((WQKV+255)/256),256>>>(Wv, wvr, C_, mszQ, WQKV);
    k_swizA<<<(unsigned)((WQKV+255)/256),256>>>(Wo, wor, C_, mszQ, WQKV);
    k_swizA<<<(unsigned)((WFF+255)/256),256>>>(W1, w1r, C_*3, (size_t)F_*C_*3, WFF);
    k_swizA<<<(unsigned)((WFF+255)/256),256>>>(W2, w2r, F_*3, (size_t)C_*F_*3, WFF);

    k_maskmul2<<<ELT_X/256,256>>>(x_in, mask, px, pxr);
    k_zb<<<(B_*C_+B_*F_)/256,256>>>(pxp, php);

    for (int L=0;L<6;L++){
        g_qkv<<<dim3(T_/128, 12, B_),256,SM_GW>>>(pxr, wqr + (size_t)L*mszQ, wkr + (size_t)L*mszQ,
                                            wvr + (size_t)L*mszQ,
                                            bq+L*C_, bk+L*C_, bv+L*C_,
                                            pq, pk, pv);
        g_sc<<<dim3(T_/128, T_/128, B_*H_),256,SM_SC>>>(pq, pk, pp);
        k_relband<<<dim3(T_/8, B_*H_),256>>>(pq, erk + L*21*64, pp);
        k_softmax<<<B_*H_*T_,256>>>(pp, mask);
        g_ctx<<<dim3(T_/128, B_*H_),256,SM_CTX>>>(pp, pv, erv + L*21*64, pc);
        g1x1<<<dim3(T_/128, C_/128, B_),256,SM_GW>>>(wor + (size_t)L*mszQ, pc, bo + L*C_, py);
        k_addln<<<dim3(T_/32,B_),512>>>(px, py, g1+L*C_, b1+L*C_, pxp, (float*)0, mask);

        gconv3p<<<dim3(T_/128, F_/128, B_),256>>>(pxp, w1r + (size_t)L*F_*C_*3, bf1+L*F_, mask,
                                                  php, C_, F_, 0, (C_*3)/32);
        gconv3p<<<dim3(T_/128, C_/128, 2*B_),256>>>(php, w2r + (size_t)L*C_*F_*3, bf2+L*C_, mask,
                                                    pq, F_, C_, 1, (F_*3)/64);
        k_red<<<ELT_X/256,256>>>(pq, bf2+L*C_, mask, py);
        k_addln<<<dim3(T_/32,B_),512>>>(px, py, g2+L*C_, b2+L*C_, (float*)0, pxr, mask);
    }
    k_maskmul<<<ELT_X/256,256>>>(px, mask, (float*)d_out);
}